// round 14
// baseline (speedup 1.0000x reference)
#include <cuda_runtime.h>
#include <math.h>
#include <stdint.h>

#define E_DIM 512
#define CHUNK 1024
#define NB 8
#define NH 8
#define HD 64
#define S_FULL 3072

// Scratch (module-static device memory: allowed; no runtime allocation)
__device__ float g_xr[NB*S_FULL*E_DIM];     // tf32-rounded x
__device__ float g_w[4][3*E_DIM*E_DIM];     // tf32-rounded Wq,Wk,Wv,Wp
__device__ float g_q[3*NB*NH*CHUNK*HD];     // [c][b][h][n][d], tf32-rounded
__device__ float g_k[3*NB*NH*CHUNK*HD];
__device__ float g_v[3*NB*NH*CHUNK*HD];
__device__ float g_attn[NB*S_FULL*E_DIM];   // [b][s][e], tf32-rounded

__device__ __forceinline__ uint32_t f2tf(float f) {
    uint32_t r; asm("cvt.rna.tf32.f32 %0, %1;" : "=r"(r) : "f"(f)); return r;
}

__device__ __forceinline__ float ex2(float x) {
    float r; asm("ex2.approx.f32 %0, %1;" : "=f"(r) : "f"(x)); return r;
}

__device__ __forceinline__ void mma_tf32(float c[4],
    uint32_t a0, uint32_t a1, uint32_t a2, uint32_t a3,
    uint32_t b0, uint32_t b1)
{
    asm volatile(
        "mma.sync.aligned.m16n8k8.row.col.f32.tf32.tf32.f32 "
        "{%0,%1,%2,%3}, {%4,%5,%6,%7}, {%8,%9}, {%0,%1,%2,%3};"
        : "+f"(c[0]), "+f"(c[1]), "+f"(c[2]), "+f"(c[3])
        : "r"(a0), "r"(a1), "r"(a2), "r"(a3), "r"(b0), "r"(b1));
}

__device__ __forceinline__ void cpa16(uint32_t dst, const float* src) {
    asm volatile("cp.async.cg.shared.global [%0], [%1], 16;" :: "r"(dst), "l"(src));
}
#define CP_COMMIT() asm volatile("cp.async.commit_group;" ::: "memory")
#define CP_WAIT1()  asm volatile("cp.async.wait_group 1;" ::: "memory")
#define CP_WAIT0()  asm volatile("cp.async.wait_group 0;" ::: "memory")

// ---------------------------------------------------------------------------
// Pre-round to tf32.
// ---------------------------------------------------------------------------
__global__ void __launch_bounds__(256) round_x_kernel(const float* __restrict__ in, int n4)
{
    int i = blockIdx.x * blockDim.x + threadIdx.x;
    if (i < n4) {
        float4 v = ((const float4*)in)[i];
        uint4 r = {f2tf(v.x), f2tf(v.y), f2tf(v.z), f2tf(v.w)};
        ((uint4*)g_xr)[i] = r;
    }
}

__global__ void __launch_bounds__(256) round_w_kernel(
    const float* __restrict__ wq, const float* __restrict__ wk,
    const float* __restrict__ wv, const float* __restrict__ wp)
{
    const float* src = blockIdx.z == 0 ? wq : blockIdx.z == 1 ? wk
                     : blockIdx.z == 2 ? wv : wp;
    int i = blockIdx.x * blockDim.x + threadIdx.x;
    float4 v = ((const float4*)src)[i];
    uint4 r = {f2tf(v.x), f2tf(v.y), f2tf(v.z), f2tf(v.w)};
    ((uint4*)g_w[blockIdx.z])[i] = r;
}

// ---------------------------------------------------------------------------
// tf32 GEMM core, 128x128xK=512. 128 threads = 4 warps (2x2), warp tile
// 64x64. cp.async double buffer, ONE sync per tile; next tile's copy is
// issued IMMEDIATELY after the barrier (max cover; race-free: passing
// sync(t) implies all warps finished compute(t-1)).
// ---------------------------------------------------------------------------
#define GSTAGE_W 10240   // words per stage (As 5120 + Bs 5120)

__device__ __forceinline__ void gemm_copy_tile(
    uint32_t sb, const float* __restrict__ Ab, const float* __restrict__ Wb,
    int n0, int kt, int cr, int cc)
{
    #pragma unroll
    for (int u = 0; u < 8; u++) {
        int r = cr + u * 16;
        cpa16(sb + (uint32_t)(r * 40 + cc) * 4, Ab + (size_t)r * E_DIM + kt + cc);
        cpa16(sb + (uint32_t)(5120 + r * 40 + cc) * 4,
              Wb + (size_t)(n0 + r) * E_DIM + kt + cc);
    }
}

__device__ __forceinline__ void gemm_kchunk(
    const uint32_t* As, const uint32_t* Bs, int ks,
    int wm, int wn, int g, int l4, float acc[4][8][4])
{
    int k0 = ks * 8 + 2 * l4;
    uint2 af0[4], af1[4];
    #pragma unroll
    for (int mi = 0; mi < 4; mi++) {
        int r0 = wm + mi * 16 + g;
        af0[mi] = *(const uint2*)(As + r0 * 40 + k0);
        af1[mi] = *(const uint2*)(As + (r0 + 8) * 40 + k0);
    }
    uint2 bf[8];
    #pragma unroll
    for (int ni = 0; ni < 8; ni++) {
        int ccol = wn + ni * 8 + g;
        bf[ni] = *(const uint2*)(Bs + ccol * 40 + k0);
    }
    #pragma unroll
    for (int mi = 0; mi < 4; mi++)
        #pragma unroll
        for (int ni = 0; ni < 8; ni++)
            mma_tf32(acc[mi][ni], af0[mi].x, af1[mi].x, af0[mi].y, af1[mi].y,
                     bf[ni].x, bf[ni].y);
}

__device__ __forceinline__ void tgemm_db(
    const float* __restrict__ Ab, const float* __restrict__ Wb, int n0,
    uint32_t* smem, float acc[4][8][4])
{
    const int tid  = threadIdx.x;
    const int lane = tid & 31, warp = tid >> 5;
    const int wm = (warp & 1) * 64, wn = (warp >> 1) * 64;
    const int g = lane >> 2, l4 = lane & 3;
    const uint32_t s_base = (uint32_t)__cvta_generic_to_shared(smem);
    const int cr = tid >> 3, cc = (tid & 7) << 2;

    #pragma unroll
    for (int mi = 0; mi < 4; mi++)
        #pragma unroll
        for (int ni = 0; ni < 8; ni++)
            #pragma unroll
            for (int e = 0; e < 4; e++) acc[mi][ni][e] = 0.f;

    gemm_copy_tile(s_base, Ab, Wb, n0, 0, cr, cc);
    CP_COMMIT();

    for (int t = 0; t < 16; t++) {
        CP_WAIT0();
        __syncthreads();
        // issue next tile's copy FIRST (max latency cover)
        if (t + 1 < 16) {
            uint32_t sb = s_base + (uint32_t)(((t + 1) & 1) * GSTAGE_W) * 4;
            gemm_copy_tile(sb, Ab, Wb, n0, (t + 1) * 32, cr, cc);
            CP_COMMIT();
        }
        const uint32_t* As = smem + (t & 1) * GSTAGE_W;
        const uint32_t* Bs = As + 5120;

        gemm_kchunk(As, Bs, 0, wm, wn, g, l4, acc);
        gemm_kchunk(As, Bs, 1, wm, wn, g, l4, acc);
        gemm_kchunk(As, Bs, 2, wm, wn, g, l4, acc);
        gemm_kchunk(As, Bs, 3, wm, wn, g, l4, acc);
    }
}

// ---------------------------------------------------------------------------
// QKV projection: grid (4, 192, 3), 128 threads. Head-major out, tf32-rounded.
// ---------------------------------------------------------------------------
__global__ void __launch_bounds__(128, 2) qkv_gemm_kernel(
    const float* __restrict__ bq, const float* __restrict__ bk,
    const float* __restrict__ bv)
{
    extern __shared__ uint32_t smem[];

    const int m0 = blockIdx.y * 128;
    const int n0 = blockIdx.x * 128;
    const int c  = (m0 % S_FULL) / CHUNK;
    const int b  = m0 / S_FULL;
    const int nrow0 = m0 % CHUNK;

    const float* W = g_w[blockIdx.z];
    const float* bias; float* outp;
    if (blockIdx.z == 0)      { bias = bq; outp = g_q; }
    else if (blockIdx.z == 1) { bias = bk; outp = g_k; }
    else                      { bias = bv; outp = g_v; }

    float acc[4][8][4];
    tgemm_db(g_xr + (size_t)m0 * E_DIM, W + (size_t)c * E_DIM * E_DIM, n0, smem, acc);

    const int lane = threadIdx.x & 31, warp = threadIdx.x >> 5;
    const int wm = (warp & 1) * 64, wn = (warp >> 1) * 64;
    const int g = lane >> 2, l4 = lane & 3;

    #pragma unroll
    for (int ni = 0; ni < 8; ni++) {
        int col = n0 + wn + ni * 8 + 2 * l4;
        int h = col >> 6, dd = col & 63;
        float b0v = bias[c * E_DIM + col];
        float b1v = bias[c * E_DIM + col + 1];
        float* ob = outp + (size_t)(((c * NB + b) * NH + h)) * CHUNK * HD;
        #pragma unroll
        for (int mi = 0; mi < 4; mi++) {
            int rl = nrow0 + wm + mi * 16 + g;
            float2 s0 = {__uint_as_float(f2tf(acc[mi][ni][0] + b0v)),
                         __uint_as_float(f2tf(acc[mi][ni][1] + b1v))};
            float2 s1 = {__uint_as_float(f2tf(acc[mi][ni][2] + b0v)),
                         __uint_as_float(f2tf(acc[mi][ni][3] + b1v))};
            *(float2*)(ob + (size_t)rl * HD + dd)       = s0;
            *(float2*)(ob + (size_t)(rl + 8) * HD + dd) = s1;
        }
    }
}

// ---------------------------------------------------------------------------
// Output projection: grid (4, 192), 128 threads. Writes d_out fp32.
// ---------------------------------------------------------------------------
__global__ void __launch_bounds__(128, 2) proj_gemm_kernel(
    const float* __restrict__ bp, float* __restrict__ out)
{
    extern __shared__ uint32_t smem[];

    const int m0 = blockIdx.y * 128;
    const int n0 = blockIdx.x * 128;
    const int c  = (m0 % S_FULL) / CHUNK;

    float acc[4][8][4];
    tgemm_db(g_attn + (size_t)m0 * E_DIM, g_w[3] + (size_t)c * E_DIM * E_DIM, n0, smem, acc);

    const int lane = threadIdx.x & 31, warp = threadIdx.x >> 5;
    const int wm = (warp & 1) * 64, wn = (warp >> 1) * 64;
    const int g = lane >> 2, l4 = lane & 3;

    #pragma unroll
    for (int ni = 0; ni < 8; ni++) {
        int col = n0 + wn + ni * 8 + 2 * l4;
        float b0v = bp[c * E_DIM + col];
        float b1v = bp[c * E_DIM + col + 1];
        #pragma unroll
        for (int mi = 0; mi < 4; mi++) {
            int m = m0 + wm + mi * 16 + g;
            float2 s0 = {acc[mi][ni][0] + b0v, acc[mi][ni][1] + b1v};
            float2 s1 = {acc[mi][ni][2] + b0v, acc[mi][ni][3] + b1v};
            *(float2*)(out + (size_t)m * E_DIM + col)       = s0;
            *(float2*)(out + (size_t)(m + 8) * E_DIM + col) = s1;
        }
    }
}

// ---------------------------------------------------------------------------
// Attention. grid (8, 1, 192), 128 threads = 4 warps; warp owns 32 q rows.
// R9 structure (64-key tiles, cp.async double buffer, mid-compute prefetch,
// no-max exp2 softmax, deferred l, accumulator-as-A-fragment PV) but with
// __launch_bounds__(128, 3): 3 CTAs/SM (12 warps). ptxas caps regs at 168;
// the ~20 spilled registers should be the loop-invariant Q fragments
// (reload ~= LDS cost) while hot sacc/Oacc stay resident.
// ---------------------------------------------------------------------------
#define KT 64
#define KS_STRIDE 72
#define VS_STRIDE 68
#define ASTAGE_W (KT*KS_STRIDE + KT*VS_STRIDE)    // 8960 words / stage
#define ATTN_SMEM_BYTES (2 * ASTAGE_W * 4)        // 71680

__global__ void __launch_bounds__(128, 3) attn_kernel()
{
    extern __shared__ uint32_t smu[];
    const uint32_t s_base = (uint32_t)__cvta_generic_to_shared(smu);

    const int z = blockIdx.z;
    const int h = z & 7, b = (z >> 3) & 7, c = z >> 6;
    const int qselA[3]  = {1, 2, 0};
    const int kvselA[3] = {2, 0, 1};
    const int qc = qselA[c], kc = kvselA[c];
    const int qtile = blockIdx.x;

    const float* Qg = g_q + ((size_t)(((qc * NB + b) * NH + h)) * CHUNK + qtile * 128) * HD;
    const float* Kg = g_k + (size_t)(((kc * NB + b) * NH + h)) * CHUNK * HD;
    const float* Vg = g_v + (size_t)(((kc * NB + b) * NH + h)) * CHUNK * HD;

    const int tid = threadIdx.x, lane = tid & 31, warp = tid >> 5;
    const int g = lane >> 2, l4 = lane & 3;
    const int wrow = warp * 32;
    const int ck = tid >> 4, cd = (tid & 15) << 2;

    // ---- prologue: issue K/V tile 0 ----
    {
        #pragma unroll
        for (int u = 0; u < 8; u++) {
            int k = ck + u * 8;
            cpa16(s_base + (uint32_t)(k * KS_STRIDE + cd) * 4, Kg + (size_t)k * HD + cd);
            cpa16(s_base + (uint32_t)(KT * KS_STRIDE + k * VS_STRIDE + cd) * 4,
                  Vg + (size_t)k * HD + cd);
        }
        CP_COMMIT();
    }

    // Q fragments for both m-tiles, pre-scaled by log2(e)/sqrt(512)
    const float sc2 = 0.044194173824159216f * 1.4426950408889634f;
    uint2 qf0[2][8], qf1[2][8];
    #pragma unroll
    for (int mt = 0; mt < 2; mt++) {
        #pragma unroll
        for (int ks = 0; ks < 8; ks++) {
            int k0 = ks * 8 + 2 * l4;
            int r0 = wrow + mt * 16 + g;
            float2 t0 = *(const float2*)(Qg + r0 * HD + k0);
            float2 t1 = *(const float2*)(Qg + (r0 + 8) * HD + k0);
            qf0[mt][ks] = {f2tf(t0.x * sc2), f2tf(t0.y * sc2)};
            qf1[mt][ks] = {f2tf(t1.x * sc2), f2tf(t1.y * sc2)};
        }
    }

    float Oacc[2][8][4];
    #pragma unroll
    for (int mt = 0; mt < 2; mt++)
        #pragma unroll
        for (int dt = 0; dt < 8; dt++)
            #pragma unroll
            for (int e = 0; e < 4; e++) Oacc[mt][dt][e] = 0.f;

    float lrun[2][2] = {{0.f, 0.f}, {0.f, 0.f}};

    for (int kt = 0; kt < 16; kt++) {
        CP_WAIT0();
        __syncthreads();

        const uint32_t* Ks = smu + (kt & 1) * ASTAGE_W;
        const uint32_t* Vs = Ks + KT * KS_STRIDE;

        // ---- S2 = Qsc @ K^T (32 x 64 per warp, k = 64), log2 domain ----
        float sacc[2][8][4];
        #pragma unroll
        for (int mt = 0; mt < 2; mt++)
            #pragma unroll
            for (int ni = 0; ni < 8; ni++)
                #pragma unroll
                for (int e = 0; e < 4; e++) sacc[mt][ni][e] = 0.f;

        #pragma unroll
        for (int ks = 0; ks < 8; ks++) {
            int k0 = ks * 8 + 2 * l4;
            #pragma unroll
            for (int ni = 0; ni < 8; ni++) {
                uint2 bfr = *(const uint2*)(Ks + (ni * 8 + g) * KS_STRIDE + k0);
                mma_tf32(sacc[0][ni], qf0[0][ks].x, qf1[0][ks].x, qf0[0][ks].y,
                         qf1[0][ks].y, bfr.x, bfr.y);
                mma_tf32(sacc[1][ni], qf0[1][ks].x, qf1[1][ks].x, qf0[1][ks].y,
                         qf1[1][ks].y, bfr.x, bfr.y);
            }
        }

        // ---- mid-compute prefetch of next K/V tile ----
        if (kt + 1 < 16) {
            uint32_t sb = s_base + (uint32_t)(((kt + 1) & 1) * ASTAGE_W) * 4;
            const float* Kt = Kg + (size_t)(kt + 1) * KT * HD;
            const float* Vt = Vg + (size_t)(kt + 1) * KT * HD;
            #pragma unroll
            for (int u = 0; u < 8; u++) {
                int k = ck + u * 8;
                cpa16(sb + (uint32_t)(k * KS_STRIDE + cd) * 4, Kt + (size_t)k * HD + cd);
                cpa16(sb + (uint32_t)(KT * KS_STRIDE + k * VS_STRIDE + cd) * 4,
                      Vt + (size_t)k * HD + cd);
            }
            CP_COMMIT();
        }

        // ---- p = exp2(s2), phase-separated (64-wide MUFU ILP) ----
        #pragma unroll
        for (int mt = 0; mt < 2; mt++) {
            #pragma unroll
            for (int ni = 0; ni < 8; ni++) {
                float p0 = ex2(sacc[mt][ni][0]);
                float p1 = ex2(sacc[mt][ni][1]);
                float p2 = ex2(sacc[mt][ni][2]);
                float p3 = ex2(sacc[mt][ni][3]);
                sacc[mt][ni][0] = p0; sacc[mt][ni][1] = p1;
                sacc[mt][ni][2] = p2; sacc[mt][ni][3] = p3;
                lrun[mt][0] += p0 + p1;
                lrun[mt][1] += p2 + p3;
            }
        }

        // ---- O += P @ V : accumulator IS the A-fragment; raw bits (trunc) ----
        #pragma unroll
        for (int ks = 0; ks < 8; ks++) {
            int kr0 = (ks * 8 + 2 * l4) * VS_STRIDE;
            #pragma unroll
            for (int dt = 0; dt < 8; dt++) {
                int dcol = dt * 8 + g;
                uint32_t b0 = Vs[kr0 + dcol];
                uint32_t b1 = Vs[kr0 + VS_STRIDE + dcol];
                mma_tf32(Oacc[0][dt],
                         __float_as_uint(sacc[0][ks][0]), __float_as_uint(sacc[0][ks][2]),
                         __float_as_uint(sacc[0][ks][1]), __float_as_uint(sacc[0][ks][3]),
                         b0, b1);
                mma_tf32(Oacc[1][dt],
                         __float_as_uint(sacc[1][ks][0]), __float_as_uint(sacc[1][ks][2]),
                         __float_as_uint(sacc[1][ks][1]), __float_as_uint(sacc[1][ks][3]),
                         b0, b1);
            }
        }
    }

    // ---- single deferred l reduction across the l4 quad ----
    #pragma unroll
    for (int mt = 0; mt < 2; mt++) {
        lrun[mt][0] += __shfl_xor_sync(0xffffffff, lrun[mt][0], 1);
        lrun[mt][0] += __shfl_xor_sync(0xffffffff, lrun[mt][0], 2);
        lrun[mt][1] += __shfl_xor_sync(0xffffffff, lrun[mt][1], 1);
        lrun[mt][1] += __shfl_xor_sync(0xffffffff, lrun[mt][1], 2);
    }

    // merge heads, rounded to tf32 (feeds proj GEMM cp.async path)
    const int nbase = c * CHUNK + qtile * 128;
    #pragma unroll
    for (int mt = 0; mt < 2; mt++) {
        float inv0 = 1.f / lrun[mt][0];
        float inv1 = 1.f / lrun[mt][1];
        #pragma unroll
        for (int dt = 0; dt < 8; dt++) {
            int d_ = dt * 8 + 2 * l4;
            int row = wrow + mt * 16 + g;
            size_t o0 = ((size_t)b * S_FULL + nbase + row) * E_DIM + h * HD + d_;
            size_t o1 = ((size_t)b * S_FULL + nbase + row + 8) * E_DIM + h * HD + d_;
            float2 s0 = {__uint_as_float(f2tf(Oacc[mt][dt][0] * inv0)),
                         __uint_as_float(f2tf(Oacc[mt][dt][1] * inv0))};
            float2 s1 = {__uint_as_float(f2tf(Oacc[mt][dt][2] * inv1)),
                         __uint_as_float(f2tf(Oacc[mt][dt][3] * inv1))};
            *(float2*)(g_attn + o0) = s0;
            *(float2*)(g_attn + o1) = s1;
        }
    }
}

// ---------------------------------------------------------------------------
extern "C" void kernel_launch(void* const* d_in, const int* in_sizes, int n_in,
                              void* d_out, int out_size)
{
    const float* x  = (const float*)d_in[0];
    const float* Wq = (const float*)d_in[1];
    const float* bq = (const float*)d_in[2];
    const float* Wk = (const float*)d_in[3];
    const float* bk = (const float*)d_in[4];
    const float* Wv = (const float*)d_in[5];
    const float* bv = (const float*)d_in[6];
    const float* Wp = (const float*)d_in[7];
    const float* bp = (const float*)d_in[8];
    float* out = (float*)d_out;

    const int gemm_smem = 2 * GSTAGE_W * 4;   // 81920
    cudaFuncSetAttribute(qkv_gemm_kernel, cudaFuncAttributeMaxDynamicSharedMemorySize, gemm_smem);
    cudaFuncSetAttribute(proj_gemm_kernel, cudaFuncAttributeMaxDynamicSharedMemorySize, gemm_smem);
    cudaFuncSetAttribute(attn_kernel, cudaFuncAttributeMaxDynamicSharedMemorySize, ATTN_SMEM_BYTES);

    const int NX4 = NB * S_FULL * E_DIM / 4;      // 3,145,728
    const int NW4 = 3 * E_DIM * E_DIM / 4;        // 196,608
    round_x_kernel<<<(NX4 + 255) / 256, 256>>>(x, NX4);
    round_w_kernel<<<dim3(NW4 / 256, 1, 4), 256>>>(Wq, Wk, Wv, Wp);

    qkv_gemm_kernel<<<dim3(4, 192, 3), 128, gemm_smem>>>(bq, bk, bv);
    attn_kernel<<<dim3(8, 1, 192), 128, ATTN_SMEM_BYTES>>>();
    proj_gemm_kernel<<<dim3(4, 192, 1), 128, gemm_smem>>>(bp, out);
}

// round 16
// speedup vs baseline: 1.3021x; 1.3021x over previous
#include <cuda_runtime.h>
#include <math.h>
#include <stdint.h>

#define E_DIM 512
#define CHUNK 1024
#define NB 8
#define NH 8
#define HD 64
#define S_FULL 3072

// Scratch (module-static device memory: allowed; no runtime allocation)
__device__ float g_xr[NB*S_FULL*E_DIM];     // tf32-rounded x
__device__ float g_w[4][3*E_DIM*E_DIM];     // tf32-rounded Wq,Wk,Wv,Wp
__device__ float g_q[3*NB*NH*CHUNK*HD];     // [c][b][h][n][d], tf32-rounded
__device__ float g_k[3*NB*NH*CHUNK*HD];     // [c][b][h][n][d]
__device__ float g_vt[3*NB*NH*HD*CHUNK];    // [c][b][h][d][n]  (TRANSPOSED V)
__device__ float g_attn[NB*S_FULL*E_DIM];   // [b][s][e], tf32-rounded

__device__ __forceinline__ uint32_t f2tf(float f) {
    uint32_t r; asm("cvt.rna.tf32.f32 %0, %1;" : "=r"(r) : "f"(f)); return r;
}

__device__ __forceinline__ float ex2(float x) {
    float r; asm("ex2.approx.f32 %0, %1;" : "=f"(r) : "f"(x)); return r;
}

__device__ __forceinline__ void mma_tf32(float c[4],
    uint32_t a0, uint32_t a1, uint32_t a2, uint32_t a3,
    uint32_t b0, uint32_t b1)
{
    asm volatile(
        "mma.sync.aligned.m16n8k8.row.col.f32.tf32.tf32.f32 "
        "{%0,%1,%2,%3}, {%4,%5,%6,%7}, {%8,%9}, {%0,%1,%2,%3};"
        : "+f"(c[0]), "+f"(c[1]), "+f"(c[2]), "+f"(c[3])
        : "r"(a0), "r"(a1), "r"(a2), "r"(a3), "r"(b0), "r"(b1));
}

__device__ __forceinline__ void cpa16(uint32_t dst, const float* src) {
    asm volatile("cp.async.cg.shared.global [%0], [%1], 16;" :: "r"(dst), "l"(src));
}
#define CP_COMMIT() asm volatile("cp.async.commit_group;" ::: "memory")
#define CP_WAIT0()  asm volatile("cp.async.wait_group 0;" ::: "memory")

// ---------------------------------------------------------------------------
// Pre-round to tf32.
// ---------------------------------------------------------------------------
__global__ void __launch_bounds__(256) round_x_kernel(const float* __restrict__ in, int n4)
{
    int i = blockIdx.x * blockDim.x + threadIdx.x;
    if (i < n4) {
        float4 v = ((const float4*)in)[i];
        uint4 r = {f2tf(v.x), f2tf(v.y), f2tf(v.z), f2tf(v.w)};
        ((uint4*)g_xr)[i] = r;
    }
}

__global__ void __launch_bounds__(256) round_w_kernel(
    const float* __restrict__ wq, const float* __restrict__ wk,
    const float* __restrict__ wv, const float* __restrict__ wp)
{
    const float* src = blockIdx.z == 0 ? wq : blockIdx.z == 1 ? wk
                     : blockIdx.z == 2 ? wv : wp;
    int i = blockIdx.x * blockDim.x + threadIdx.x;
    float4 v = ((const float4*)src)[i];
    uint4 r = {f2tf(v.x), f2tf(v.y), f2tf(v.z), f2tf(v.w)};
    ((uint4*)g_w[blockIdx.z])[i] = r;
}

// ---------------------------------------------------------------------------
// tf32 GEMM core, 128x128xK=512. 128 threads = 4 warps (2x2), warp tile
// 64x64. cp.async double buffer, ONE sync per tile, mid-compute prefetch
// (exact R9 structure — known good).
// ---------------------------------------------------------------------------
#define GSTAGE_W 10240   // words per stage (As 5120 + Bs 5120)

__device__ __forceinline__ void gemm_copy_tile(
    uint32_t sb, const float* __restrict__ Ab, const float* __restrict__ Wb,
    int n0, int kt, int cr, int cc)
{
    #pragma unroll
    for (int u = 0; u < 8; u++) {
        int r = cr + u * 16;
        cpa16(sb + (uint32_t)(r * 40 + cc) * 4, Ab + (size_t)r * E_DIM + kt + cc);
        cpa16(sb + (uint32_t)(5120 + r * 40 + cc) * 4,
              Wb + (size_t)(n0 + r) * E_DIM + kt + cc);
    }
}

__device__ __forceinline__ void gemm_kchunk(
    const uint32_t* As, const uint32_t* Bs, int ks,
    int wm, int wn, int g, int l4, float acc[4][8][4])
{
    int k0 = ks * 8 + 2 * l4;
    uint2 af0[4], af1[4];
    #pragma unroll
    for (int mi = 0; mi < 4; mi++) {
        int r0 = wm + mi * 16 + g;
        af0[mi] = *(const uint2*)(As + r0 * 40 + k0);
        af1[mi] = *(const uint2*)(As + (r0 + 8) * 40 + k0);
    }
    uint2 bf[8];
    #pragma unroll
    for (int ni = 0; ni < 8; ni++) {
        int ccol = wn + ni * 8 + g;
        bf[ni] = *(const uint2*)(Bs + ccol * 40 + k0);
    }
    #pragma unroll
    for (int mi = 0; mi < 4; mi++)
        #pragma unroll
        for (int ni = 0; ni < 8; ni++)
            mma_tf32(acc[mi][ni], af0[mi].x, af1[mi].x, af0[mi].y, af1[mi].y,
                     bf[ni].x, bf[ni].y);
}

__device__ __forceinline__ void tgemm_db(
    const float* __restrict__ Ab, const float* __restrict__ Wb, int n0,
    uint32_t* smem, float acc[4][8][4])
{
    const int tid  = threadIdx.x;
    const int lane = tid & 31, warp = tid >> 5;
    const int wm = (warp & 1) * 64, wn = (warp >> 1) * 64;
    const int g = lane >> 2, l4 = lane & 3;
    const uint32_t s_base = (uint32_t)__cvta_generic_to_shared(smem);
    const int cr = tid >> 3, cc = (tid & 7) << 2;

    #pragma unroll
    for (int mi = 0; mi < 4; mi++)
        #pragma unroll
        for (int ni = 0; ni < 8; ni++)
            #pragma unroll
            for (int e = 0; e < 4; e++) acc[mi][ni][e] = 0.f;

    gemm_copy_tile(s_base, Ab, Wb, n0, 0, cr, cc);
    CP_COMMIT();

    for (int t = 0; t < 16; t++) {
        CP_WAIT0();
        __syncthreads();
        const uint32_t* As = smem + (t & 1) * GSTAGE_W;
        const uint32_t* Bs = As + 5120;

        gemm_kchunk(As, Bs, 0, wm, wn, g, l4, acc);
        if (t + 1 < 16) {
            uint32_t sb = s_base + (uint32_t)(((t + 1) & 1) * GSTAGE_W) * 4;
            gemm_copy_tile(sb, Ab, Wb, n0, (t + 1) * 32, cr, cc);
            CP_COMMIT();
        }
        gemm_kchunk(As, Bs, 1, wm, wn, g, l4, acc);
        gemm_kchunk(As, Bs, 2, wm, wn, g, l4, acc);
        gemm_kchunk(As, Bs, 3, wm, wn, g, l4, acc);
    }
}

// ---------------------------------------------------------------------------
// QKV projection: grid (4, 192, 3), 128 threads. Q/K head-major [n][d];
// V transposed head-major [d][n]. All tf32-rounded.
// ---------------------------------------------------------------------------
__global__ void __launch_bounds__(128, 2) qkv_gemm_kernel(
    const float* __restrict__ bq, const float* __restrict__ bk,
    const float* __restrict__ bv)
{
    extern __shared__ uint32_t smem[];

    const int m0 = blockIdx.y * 128;
    const int n0 = blockIdx.x * 128;
    const int c  = (m0 % S_FULL) / CHUNK;
    const int b  = m0 / S_FULL;
    const int nrow0 = m0 % CHUNK;

    const float* W = g_w[blockIdx.z];
    const float* bias = blockIdx.z == 0 ? bq : blockIdx.z == 1 ? bk : bv;

    float acc[4][8][4];
    tgemm_db(g_xr + (size_t)m0 * E_DIM, W + (size_t)c * E_DIM * E_DIM, n0, smem, acc);

    const int lane = threadIdx.x & 31, warp = threadIdx.x >> 5;
    const int wm = (warp & 1) * 64, wn = (warp >> 1) * 64;
    const int g = lane >> 2, l4 = lane & 3;

    if (blockIdx.z == 2) {
        // V transposed: g_vt[c][b][h][d][n]
        #pragma unroll
        for (int ni = 0; ni < 8; ni++) {
            int col = n0 + wn + ni * 8 + 2 * l4;
            int h = col >> 6, dd = col & 63;
            float b0v = bias[c * E_DIM + col];
            float b1v = bias[c * E_DIM + col + 1];
            float* ob = g_vt + (size_t)(((c * NB + b) * NH + h)) * HD * CHUNK;
            #pragma unroll
            for (int mi = 0; mi < 4; mi++) {
                int rl = nrow0 + wm + mi * 16 + g;
                ob[(size_t)dd * CHUNK + rl]           = __uint_as_float(f2tf(acc[mi][ni][0] + b0v));
                ob[(size_t)(dd + 1) * CHUNK + rl]     = __uint_as_float(f2tf(acc[mi][ni][1] + b1v));
                ob[(size_t)dd * CHUNK + rl + 8]       = __uint_as_float(f2tf(acc[mi][ni][2] + b0v));
                ob[(size_t)(dd + 1) * CHUNK + rl + 8] = __uint_as_float(f2tf(acc[mi][ni][3] + b1v));
            }
        }
    } else {
        float* outp = (blockIdx.z == 0) ? g_q : g_k;
        #pragma unroll
        for (int ni = 0; ni < 8; ni++) {
            int col = n0 + wn + ni * 8 + 2 * l4;
            int h = col >> 6, dd = col & 63;
            float b0v = bias[c * E_DIM + col];
            float b1v = bias[c * E_DIM + col + 1];
            float* ob = outp + (size_t)(((c * NB + b) * NH + h)) * CHUNK * HD;
            #pragma unroll
            for (int mi = 0; mi < 4; mi++) {
                int rl = nrow0 + wm + mi * 16 + g;
                float2 s0 = {__uint_as_float(f2tf(acc[mi][ni][0] + b0v)),
                             __uint_as_float(f2tf(acc[mi][ni][1] + b1v))};
                float2 s1 = {__uint_as_float(f2tf(acc[mi][ni][2] + b0v)),
                             __uint_as_float(f2tf(acc[mi][ni][3] + b1v))};
                *(float2*)(ob + (size_t)rl * HD + dd)       = s0;
                *(float2*)(ob + (size_t)(rl + 8) * HD + dd) = s1;
            }
        }
    }
}

// ---------------------------------------------------------------------------
// Output projection: grid (4, 192), 128 threads. Writes d_out fp32.
// ---------------------------------------------------------------------------
__global__ void __launch_bounds__(128, 2) proj_gemm_kernel(
    const float* __restrict__ bp, float* __restrict__ out)
{
    extern __shared__ uint32_t smem[];

    const int m0 = blockIdx.y * 128;
    const int n0 = blockIdx.x * 128;
    const int c  = (m0 % S_FULL) / CHUNK;

    float acc[4][8][4];
    tgemm_db(g_attn + (size_t)m0 * E_DIM, g_w[3] + (size_t)c * E_DIM * E_DIM, n0, smem, acc);

    const int lane = threadIdx.x & 31, warp = threadIdx.x >> 5;
    const int wm = (warp & 1) * 64, wn = (warp >> 1) * 64;
    const int g = lane >> 2, l4 = lane & 3;

    #pragma unroll
    for (int ni = 0; ni < 8; ni++) {
        int col = n0 + wn + ni * 8 + 2 * l4;
        float b0v = bp[c * E_DIM + col];
        float b1v = bp[c * E_DIM + col + 1];
        #pragma unroll
        for (int mi = 0; mi < 4; mi++) {
            int m = m0 + wm + mi * 16 + g;
            float2 s0 = {acc[mi][ni][0] + b0v, acc[mi][ni][1] + b1v};
            float2 s1 = {acc[mi][ni][2] + b0v, acc[mi][ni][3] + b1v};
            *(float2*)(out + (size_t)m * E_DIM + col)       = s0;
            *(float2*)(out + (size_t)(m + 8) * E_DIM + col) = s1;
        }
    }
}

// ---------------------------------------------------------------------------
// Attention. grid (8, 1, 192), 128 threads = 4 warps; warp owns 32 q rows.
// Exact R9 structure (64-key tiles, cp.async double buffer, mid-compute
// prefetch, no-max exp2 softmax, deferred l, accumulator-as-A-fragment PV,
// (128,2)) EXCEPT: V is d-major ([d][n], stride 72) so each PV B-fragment
// pair (V[k][n], V[k+1][n]) is one LDS.64 — V LDS issues halved (128->64
// per tile per warp). Bank-clean: word addr mod 32 = 8g+2l4 per phase.
// ---------------------------------------------------------------------------
#define KT 64
#define KS_STRIDE 72
#define VT_STRIDE 72
#define VOFF (KT*KS_STRIDE)                       // 4608 words
#define ASTAGE_W (KT*KS_STRIDE + HD*VT_STRIDE)    // 9216 words / stage
#define ATTN_SMEM_BYTES (2 * ASTAGE_W * 4)        // 73728

__global__ void __launch_bounds__(128, 2) attn_kernel()
{
    extern __shared__ uint32_t smu[];
    const uint32_t s_base = (uint32_t)__cvta_generic_to_shared(smu);

    const int z = blockIdx.z;
    const int h = z & 7, b = (z >> 3) & 7, c = z >> 6;
    const int qselA[3]  = {1, 2, 0};
    const int kvselA[3] = {2, 0, 1};
    const int qc = qselA[c], kc = kvselA[c];
    const int qtile = blockIdx.x;

    const float* Qg  = g_q  + ((size_t)(((qc * NB + b) * NH + h)) * CHUNK + qtile * 128) * HD;
    const float* Kg  = g_k  + (size_t)(((kc * NB + b) * NH + h)) * CHUNK * HD;
    const float* Vtg = g_vt + (size_t)(((kc * NB + b) * NH + h)) * HD * CHUNK;

    const int tid = threadIdx.x, lane = tid & 31, warp = tid >> 5;
    const int g = lane >> 2, l4 = lane & 3;
    const int wrow = warp * 32;
    const int ck = tid >> 4, cd = (tid & 15) << 2;

    // ---- K/V tile copy (both tiles 64 rows x 64 floats) ----
    auto issue_tile = [&](int tt) {
        uint32_t sb = s_base + (uint32_t)((tt & 1) * ASTAGE_W) * 4;
        const float* Kt = Kg + (size_t)tt * KT * HD;       // rows k, contiguous d
        const float* Vt = Vtg + (size_t)tt * KT;           // rows d, stride CHUNK
        #pragma unroll
        for (int u = 0; u < 8; u++) {
            int r = ck + u * 8;
            cpa16(sb + (uint32_t)(r * KS_STRIDE + cd) * 4, Kt + (size_t)r * HD + cd);
            cpa16(sb + (uint32_t)(VOFF + r * VT_STRIDE + cd) * 4,
                  Vt + (size_t)r * CHUNK + cd);
        }
    };

    issue_tile(0); CP_COMMIT();

    // Q fragments for both m-tiles, pre-scaled by log2(e)/sqrt(512)
    const float sc2 = 0.044194173824159216f * 1.4426950408889634f;
    uint2 qf0[2][8], qf1[2][8];
    #pragma unroll
    for (int mt = 0; mt < 2; mt++) {
        #pragma unroll
        for (int ks = 0; ks < 8; ks++) {
            int k0 = ks * 8 + 2 * l4;
            int r0 = wrow + mt * 16 + g;
            float2 t0 = *(const float2*)(Qg + r0 * HD + k0);
            float2 t1 = *(const float2*)(Qg + (r0 + 8) * HD + k0);
            qf0[mt][ks] = {f2tf(t0.x * sc2), f2tf(t0.y * sc2)};
            qf1[mt][ks] = {f2tf(t1.x * sc2), f2tf(t1.y * sc2)};
        }
    }

    float Oacc[2][8][4];
    #pragma unroll
    for (int mt = 0; mt < 2; mt++)
        #pragma unroll
        for (int dt = 0; dt < 8; dt++)
            #pragma unroll
            for (int e = 0; e < 4; e++) Oacc[mt][dt][e] = 0.f;

    float lrun[2][2] = {{0.f, 0.f}, {0.f, 0.f}};

    for (int kt = 0; kt < 16; kt++) {
        CP_WAIT0();
        __syncthreads();

        const uint32_t* Ks = smu + (kt & 1) * ASTAGE_W;
        const uint32_t* Vs = Ks + VOFF;

        // ---- S2 = Qsc @ K^T (32 x 64 per warp, k = 64), log2 domain ----
        float sacc[2][8][4];
        #pragma unroll
        for (int mt = 0; mt < 2; mt++)
            #pragma unroll
            for (int ni = 0; ni < 8; ni++)
                #pragma unroll
                for (int e = 0; e < 4; e++) sacc[mt][ni][e] = 0.f;

        #pragma unroll
        for (int ks = 0; ks < 8; ks++) {
            int k0 = ks * 8 + 2 * l4;
            #pragma unroll
            for (int ni = 0; ni < 8; ni++) {
                uint2 bfr = *(const uint2*)(Ks + (ni * 8 + g) * KS_STRIDE + k0);
                mma_tf32(sacc[0][ni], qf0[0][ks].x, qf1[0][ks].x, qf0[0][ks].y,
                         qf1[0][ks].y, bfr.x, bfr.y);
                mma_tf32(sacc[1][ni], qf0[1][ks].x, qf1[1][ks].x, qf0[1][ks].y,
                         qf1[1][ks].y, bfr.x, bfr.y);
            }
        }

        // ---- mid-compute prefetch of next K/V tile ----
        if (kt + 1 < 16) { issue_tile(kt + 1); CP_COMMIT(); }

        // ---- p = exp2(s2), phase-separated (64-wide MUFU ILP) ----
        #pragma unroll
        for (int mt = 0; mt < 2; mt++) {
            #pragma unroll
            for (int ni = 0; ni < 8; ni++) {
                float p0 = ex2(sacc[mt][ni][0]);
                float p1 = ex2(sacc[mt][ni][1]);
                float p2 = ex2(sacc[mt][ni][2]);
                float p3 = ex2(sacc[mt][ni][3]);
                sacc[mt][ni][0] = p0; sacc[mt][ni][1] = p1;
                sacc[mt][ni][2] = p2; sacc[mt][ni][3] = p3;
                lrun[mt][0] += p0 + p1;
                lrun[mt][1] += p2 + p3;
            }
        }

        // ---- O += P @ V : V d-major, B-fragment = single LDS.64 ----
        #pragma unroll
        for (int ks = 0; ks < 8; ks++) {
            int k0 = ks * 8 + 2 * l4;
            #pragma unroll
            for (int dt = 0; dt < 8; dt++) {
                int dcol = dt * 8 + g;
                uint2 vv = *(const uint2*)(Vs + dcol * VT_STRIDE + k0);
                mma_tf32(Oacc[0][dt],
                         __float_as_uint(sacc[0][ks][0]), __float_as_uint(sacc[0][ks][2]),
                         __float_as_uint(sacc[0][ks][1]), __float_as_uint(sacc[0][ks][3]),
                         vv.x, vv.y);
                mma_tf32(Oacc[1][dt],
                         __float_as_uint(sacc[1][ks][0]), __float_as_uint(sacc[1][ks][2]),
                         __float_as_uint(sacc[1][ks][1]), __float_as_uint(sacc[1][ks][3]),
                         vv.x, vv.y);
            }
        }
    }

    // ---- single deferred l reduction across the l4 quad ----
    #pragma unroll
    for (int mt = 0; mt < 2; mt++) {
        lrun[mt][0] += __shfl_xor_sync(0xffffffff, lrun[mt][0], 1);
        lrun[mt][0] += __shfl_xor_sync(0xffffffff, lrun[mt][0], 2);
        lrun[mt][1] += __shfl_xor_sync(0xffffffff, lrun[mt][1], 1);
        lrun[mt][1] += __shfl_xor_sync(0xffffffff, lrun[mt][1], 2);
    }

    // merge heads, rounded to tf32 (feeds proj GEMM cp.async path)
    const int nbase = c * CHUNK + qtile * 128;
    #pragma unroll
    for (int mt = 0; mt < 2; mt++) {
        float inv0 = 1.f / lrun[mt][0];
        float inv1 = 1.f / lrun[mt][1];
        #pragma unroll
        for (int dt = 0; dt < 8; dt++) {
            int d_ = dt * 8 + 2 * l4;
            int row = wrow + mt * 16 + g;
            size_t o0 = ((size_t)b * S_FULL + nbase + row) * E_DIM + h * HD + d_;
            size_t o1 = ((size_t)b * S_FULL + nbase + row + 8) * E_DIM + h * HD + d_;
            float2 s0 = {__uint_as_float(f2tf(Oacc[mt][dt][0] * inv0)),
                         __uint_as_float(f2tf(Oacc[mt][dt][1] * inv0))};
            float2 s1 = {__uint_as_float(f2tf(Oacc[mt][dt][2] * inv1)),
                         __uint_as_float(f2tf(Oacc[mt][dt][3] * inv1))};
            *(float2*)(g_attn + o0) = s0;
            *(float2*)(g_attn + o1) = s1;
        }
    }
}

// ---------------------------------------------------------------------------
extern "C" void kernel_launch(void* const* d_in, const int* in_sizes, int n_in,
                              void* d_out, int out_size)
{
    const float* x  = (const float*)d_in[0];
    const float* Wq = (const float*)d_in[1];
    const float* bq = (const float*)d_in[2];
    const float* Wk = (const float*)d_in[3];
    const float* bk = (const float*)d_in[4];
    const float* Wv = (const float*)d_in[5];
    const float* bv = (const float*)d_in[6];
    const float* Wp = (const float*)d_in[7];
    const float* bp = (const float*)d_in[8];
    float* out = (float*)d_out;

    const int gemm_smem = 2 * GSTAGE_W * 4;   // 81920
    cudaFuncSetAttribute(qkv_gemm_kernel, cudaFuncAttributeMaxDynamicSharedMemorySize, gemm_smem);
    cudaFuncSetAttribute(proj_gemm_kernel, cudaFuncAttributeMaxDynamicSharedMemorySize, gemm_smem);
    cudaFuncSetAttribute(attn_kernel, cudaFuncAttributeMaxDynamicSharedMemorySize, ATTN_SMEM_BYTES);

    const int NX4 = NB * S_FULL * E_DIM / 4;      // 3,145,728
    const int NW4 = 3 * E_DIM * E_DIM / 4;        // 196,608
    round_x_kernel<<<(NX4 + 255) / 256, 256>>>(x, NX4);
    round_w_kernel<<<dim3(NW4 / 256, 1, 4), 256>>>(Wq, Wk, Wv, Wp);

    qkv_gemm_kernel<<<dim3(4, 192, 3), 128, gemm_smem>>>(bq, bk, bv);
    attn_kernel<<<dim3(8, 1, 192), 128, ATTN_SMEM_BYTES>>>();
    proj_gemm_kernel<<<dim3(4, 192, 1), 128, gemm_smem>>>(bp, out);
}